// round 1
// baseline (speedup 1.0000x reference)
#include <cuda_runtime.h>
#include <cuda_bf16.h>
#include <cstdint>

// Problem constants
#define B_DIM   2048
#define P_DIM   50
#define K_DIM   28672            // 512*7*8
#define N_PAD   64               // P padded to 64 for MMA tiling
#define KS      28               // K splits
#define KCHUNK  (K_DIM / KS)     // 1024
#define KB      64               // K per smem iteration
#define NITER   (KCHUNK / KB)    // 16
#define MT      128              // M tile (rows of x per block)
#define MTILES  (B_DIM / MT)     // 16

// Static device scratch (allocation-free rule)
__device__ __nv_bfloat16 g_proto[(size_t)N_PAD * K_DIM];              // 3.5 MB
__device__ float         g_p2[N_PAD];
__device__ float         g_xp[(size_t)KS * MTILES * MT * N_PAD];      // 14.7 MB
__device__ float         g_x2[(size_t)KS * B_DIM];                    // 229 KB

// ---------------------------------------------------------------------------
// Kernel 1: prototype fp32 -> bf16 (padded rows zeroed), p2 row norms (fp32)
// ---------------------------------------------------------------------------
__global__ void __launch_bounds__(256) prep_kernel(const float* __restrict__ proto) {
    const int p = blockIdx.x;   // 0..63
    const int t = threadIdx.x;  // 256
    float s = 0.f;
    __nv_bfloat16* dst = g_proto + (size_t)p * K_DIM;
    if (p < P_DIM) {
        const float* row = proto + (size_t)p * K_DIM;
        // 28672 / (256*4) = 28 exact iterations
        for (int k = t * 4; k < K_DIM; k += 256 * 4) {
            float4 v = *(const float4*)(row + k);
            s += v.x * v.x + v.y * v.y + v.z * v.z + v.w * v.w;
            __nv_bfloat162 lo = __floats2bfloat162_rn(v.x, v.y);
            __nv_bfloat162 hi = __floats2bfloat162_rn(v.z, v.w);
            *(__nv_bfloat162*)(dst + k)     = lo;
            *(__nv_bfloat162*)(dst + k + 2) = hi;
        }
    } else {
        const __nv_bfloat162 z = __floats2bfloat162_rn(0.f, 0.f);
        for (int k = t * 4; k < K_DIM; k += 256 * 4) {
            *(__nv_bfloat162*)(dst + k)     = z;
            *(__nv_bfloat162*)(dst + k + 2) = z;
        }
    }
    // block reduce s -> g_p2[p]
    __shared__ float red[256];
    red[t] = s;
    __syncthreads();
    for (int off = 128; off > 0; off >>= 1) {
        if (t < off) red[t] += red[t + off];
        __syncthreads();
    }
    if (t == 0) g_p2[p] = red[0];
}

// ---------------------------------------------------------------------------
// Kernel 2: fused split-K GEMM (bf16 HMMA, fp32 accum) + x^2 row partials
// grid (MTILES, KS), 256 threads = 8 warps; warp w owns rows [w*16, w*16+16)
// ---------------------------------------------------------------------------
__global__ void __launch_bounds__(256) gemm_kernel(const float* __restrict__ x) {
    __shared__ __nv_bfloat16 As[MT][72];      // pitch 72 bf16 = 144 B (conflict-friendly)
    __shared__ __nv_bfloat16 Bs[N_PAD][72];
    __shared__ float x2s[256];

    const int mt   = blockIdx.x;
    const int ks   = blockIdx.y;
    const int t    = threadIdx.x;
    const int warp = t >> 5;
    const int lane = t & 31;
    const int b0   = mt * MT;
    const int k0   = ks * KCHUNK;

    // x loading: row fixed per thread (2 threads/row, 32 floats each per iter)
    const int xrow = t >> 1;
    const int xcol = (t & 1) * 32;
    const float* xbase = x + (size_t)(b0 + xrow) * K_DIM + k0 + xcol;

    // proto loading: 64 rows, 4 threads/row, 2x 16B each per iter
    const int prow = t >> 2;
    const int pcol = (t & 3) * 8;
    const __nv_bfloat16* pbase = g_proto + (size_t)prow * K_DIM + k0 + pcol;

    float acc[8][4];
    #pragma unroll
    for (int j = 0; j < 8; j++)
        #pragma unroll
        for (int c = 0; c < 4; c++) acc[j][c] = 0.f;
    float x2 = 0.f;

    float4 xr[8];
    uint4  pr0, pr1;

    // prefetch iteration 0
    #pragma unroll
    for (int i = 0; i < 8; i++) xr[i] = *(const float4*)(xbase + i * 4);
    pr0 = *(const uint4*)(pbase);
    pr1 = *(const uint4*)(pbase + 32);

    const int arow  = warp * 16 + (lane >> 2);
    const int kfrac = (lane & 3) * 2;

    for (int it = 0; it < NITER; ++it) {
        __syncthreads();   // previous iteration's MMA reads done
        // convert + store A tile; accumulate x^2 in fp32 from registers
        #pragma unroll
        for (int i = 0; i < 8; i++) {
            float4 v = xr[i];
            x2 += v.x * v.x + v.y * v.y + v.z * v.z + v.w * v.w;
            __nv_bfloat162 lo = __floats2bfloat162_rn(v.x, v.y);
            __nv_bfloat162 hi = __floats2bfloat162_rn(v.z, v.w);
            *(__nv_bfloat162*)&As[xrow][xcol + i * 4]     = lo;
            *(__nv_bfloat162*)&As[xrow][xcol + i * 4 + 2] = hi;
        }
        // store B tile (8-byte stores: pitch 144 B keeps 8B alignment)
        *(uint2*)&Bs[prow][pcol]      = make_uint2(pr0.x, pr0.y);
        *(uint2*)&Bs[prow][pcol + 4]  = make_uint2(pr0.z, pr0.w);
        *(uint2*)&Bs[prow][pcol + 32] = make_uint2(pr1.x, pr1.y);
        *(uint2*)&Bs[prow][pcol + 36] = make_uint2(pr1.z, pr1.w);
        __syncthreads();

        // prefetch next iteration (overlaps with MMA below)
        if (it + 1 < NITER) {
            const float* xn = xbase + (it + 1) * KB;
            #pragma unroll
            for (int i = 0; i < 8; i++) xr[i] = *(const float4*)(xn + i * 4);
            const __nv_bfloat16* pn = pbase + (it + 1) * KB;
            pr0 = *(const uint4*)(pn);
            pr1 = *(const uint4*)(pn + 32);
        }

        // MMA: 4 k16-steps x 8 n8-tiles, m16n8k16 bf16->fp32
        #pragma unroll
        for (int kk = 0; kk < 4; ++kk) {
            const int kb = kk * 16 + kfrac;
            uint32_t a0 = *(const uint32_t*)&As[arow][kb];
            uint32_t a1 = *(const uint32_t*)&As[arow + 8][kb];
            uint32_t a2 = *(const uint32_t*)&As[arow][kb + 8];
            uint32_t a3 = *(const uint32_t*)&As[arow + 8][kb + 8];
            #pragma unroll
            for (int j = 0; j < 8; j++) {
                const int n = j * 8 + (lane >> 2);
                uint32_t bb0 = *(const uint32_t*)&Bs[n][kb];
                uint32_t bb1 = *(const uint32_t*)&Bs[n][kb + 8];
                asm volatile(
                    "mma.sync.aligned.m16n8k16.row.col.f32.bf16.bf16.f32 "
                    "{%0,%1,%2,%3}, {%4,%5,%6,%7}, {%8,%9}, {%0,%1,%2,%3};\n"
                    : "+f"(acc[j][0]), "+f"(acc[j][1]), "+f"(acc[j][2]), "+f"(acc[j][3])
                    : "r"(a0), "r"(a1), "r"(a2), "r"(a3), "r"(bb0), "r"(bb1));
            }
        }
    }

    // write xp partials (deterministic: private scratch slice per block)
    float* outp = g_xp + ((size_t)ks * MTILES + mt) * (MT * N_PAD);
    const int crow = warp * 16 + (lane >> 2);
    const int ccol = (lane & 3) * 2;
    #pragma unroll
    for (int j = 0; j < 8; j++) {
        const int n = j * 8 + ccol;
        *(float2*)&outp[(size_t)crow * N_PAD + n]       = make_float2(acc[j][0], acc[j][1]);
        *(float2*)&outp[(size_t)(crow + 8) * N_PAD + n] = make_float2(acc[j][2], acc[j][3]);
    }

    // write x^2 partials (combine the 2 threads per row)
    x2s[t] = x2;
    __syncthreads();
    if (t < 128) g_x2[(size_t)ks * B_DIM + b0 + t] = x2s[2 * t] + x2s[2 * t + 1];
}

// ---------------------------------------------------------------------------
// Kernel 3: reduce split-K partials, apply relu(x2 + p2 - 2*xp)
// ---------------------------------------------------------------------------
__global__ void __launch_bounds__(64) epilogue_kernel(float* __restrict__ out) {
    const int b = blockIdx.x;
    const int p = threadIdx.x;  // 0..63
    const int mt = b >> 7, r = b & 127;

    float xp = 0.f;
    #pragma unroll
    for (int ks = 0; ks < KS; ++ks)
        xp += g_xp[((size_t)ks * MTILES + mt) * (MT * N_PAD) + (size_t)r * N_PAD + p];

    __shared__ float x2sh;
    if (p == 0) {
        float s = 0.f;
        #pragma unroll
        for (int ks = 0; ks < KS; ++ks) s += g_x2[(size_t)ks * B_DIM + b];
        x2sh = s;
    }
    __syncthreads();

    if (p < P_DIM) {
        float d = x2sh + g_p2[p] - 2.f * xp;
        out[(size_t)b * P_DIM + p] = d > 0.f ? d : 0.f;
    }
}

// ---------------------------------------------------------------------------
extern "C" void kernel_launch(void* const* d_in, const int* in_sizes, int n_in,
                              void* d_out, int out_size) {
    // metadata order: x [B,C,H,W] (58,720,256), prototype [P,C,H,W] (1,433,600)
    const float* x     = (const float*)d_in[0];
    const float* proto = (const float*)d_in[1];
    if (in_sizes[0] == P_DIM * K_DIM) {  // defensive: swap if order differs
        x     = (const float*)d_in[1];
        proto = (const float*)d_in[0];
    }
    float* out = (float*)d_out;

    prep_kernel<<<N_PAD, 256>>>(proto);
    gemm_kernel<<<dim3(MTILES, KS), 256>>>(x);
    epilogue_kernel<<<B_DIM, 64>>>(out);
}

// round 2
// speedup vs baseline: 1.9389x; 1.9389x over previous
#include <cuda_runtime.h>
#include <cuda_bf16.h>
#include <cstdint>

// Problem constants
#define B_DIM   2048
#define P_DIM   50
#define K_DIM   28672            // 512*7*8
#define NP      56               // P padded to 56 (7 n8-tiles)
#define KS      28               // K splits
#define KCHUNK  (K_DIM / KS)     // 1024
#define KB      32               // K per pipeline stage
#define NITER   (KCHUNK / KB)    // 32
#define MT      128              // M tile
#define MTILES  (B_DIM / MT)     // 16
#define STAGES  3
#define APITCH  40               // fp32 pitch for x tile (conflict-free fragments)
#define BPITCH  40               // bf16 pitch for proto tile

#define AS_STAGE (MT * APITCH)           // floats per A stage: 5120
#define BS_STAGE (NP * BPITCH)           // bf16 per B stage: 2240
#define SMEM_BYTES (STAGES * (AS_STAGE * 4 + BS_STAGE * 2))   // 74880

// Static device scratch (allocation-free rule)
__device__ __align__(16) __nv_bfloat16 g_proto[(size_t)NP * K_DIM];       // 3.1 MB
__device__ float g_p2p[8][NP];                                             // p2 partials
__device__ float g_xp[(size_t)KS * MTILES * MT * NP];                      // 12.8 MB
__device__ float g_x2[(size_t)KS * B_DIM];                                 // 229 KB

// ---------------------------------------------------------------------------
// Kernel 1: prototype fp32 -> bf16 (rows 50..55 zeroed) + p2 partial sums
// grid (NP, 8), 128 threads: block (p, c) handles K/8 = 3584 elems of row p
// ---------------------------------------------------------------------------
__global__ void __launch_bounds__(128) prep_kernel(const float* __restrict__ proto) {
    const int p = blockIdx.x;
    const int c = blockIdx.y;
    const int t = threadIdx.x;
    const size_t base = (size_t)p * K_DIM + (size_t)c * 3584;
    __nv_bfloat16* dst = g_proto + base;
    float s = 0.f;
    if (p < P_DIM) {
        const float* src = proto + base;
        #pragma unroll
        for (int k = t * 4; k < 3584; k += 512) {
            float4 v = *(const float4*)(src + k);
            s += v.x * v.x + v.y * v.y + v.z * v.z + v.w * v.w;
            *(__nv_bfloat162*)(dst + k)     = __floats2bfloat162_rn(v.x, v.y);
            *(__nv_bfloat162*)(dst + k + 2) = __floats2bfloat162_rn(v.z, v.w);
        }
    } else {
        const __nv_bfloat162 z = __floats2bfloat162_rn(0.f, 0.f);
        #pragma unroll
        for (int k = t * 4; k < 3584; k += 512) {
            *(__nv_bfloat162*)(dst + k)     = z;
            *(__nv_bfloat162*)(dst + k + 2) = z;
        }
    }
    // block reduce
    __shared__ float red[128];
    red[t] = s;
    __syncthreads();
    for (int off = 64; off > 0; off >>= 1) {
        if (t < off) red[t] += red[t + off];
        __syncthreads();
    }
    if (t == 0) g_p2p[c][p] = red[0];
}

// ---------------------------------------------------------------------------
// Kernel 2: split-K GEMM, 3-stage cp.async pipeline, x staged fp32 in smem,
// bf16 convert + x^2 accumulation done in fragment registers.
// grid (MTILES, KS), 256 threads = 8 warps; warp w owns rows [w*16, w*16+16)
// ---------------------------------------------------------------------------
__device__ __forceinline__ void cpa16(uint32_t saddr, const void* gaddr) {
    asm volatile("cp.async.cg.shared.global [%0], [%1], 16;\n"
                 :: "r"(saddr), "l"(gaddr));
}
__device__ __forceinline__ void cpa_commit() {
    asm volatile("cp.async.commit_group;\n" ::: "memory");
}
__device__ __forceinline__ void cpa_wait2() {
    asm volatile("cp.async.wait_group 2;\n" ::: "memory");
}
__device__ __forceinline__ uint32_t pack_bf16x2(float2 v) {
    __nv_bfloat162 h = __floats2bfloat162_rn(v.x, v.y);
    return *(uint32_t*)&h;
}

__global__ void __launch_bounds__(256, 3) gemm_kernel(const float* __restrict__ x) {
    extern __shared__ char smem[];
    float* As = (float*)smem;                                     // [STAGES][MT][APITCH]
    __nv_bfloat16* Bs = (__nv_bfloat16*)(smem + STAGES * AS_STAGE * 4);  // [STAGES][NP][BPITCH]

    const int mt   = blockIdx.x;
    const int ks   = blockIdx.y;
    const int t    = threadIdx.x;
    const int warp = t >> 5;
    const int lane = t & 31;
    const int q    = lane & 3;
    const int b0   = mt * MT;
    const int k0   = ks * KCHUNK;

    // cp.async source/dest mapping
    const int xrr = t >> 3;          // 0..31 (row within 32-row pass)
    const int xch = t & 7;           // 16B chunk within row (8 chunks = 128 B)
    const float* xg0 = x + (size_t)(b0 + xrr) * K_DIM + k0 + xch * 4;
    const uint32_t As_u = (uint32_t)__cvta_generic_to_shared(As);
    const uint32_t Bs_u = (uint32_t)__cvta_generic_to_shared(Bs);

    const int prr = t >> 2;          // 0..63 (only <NP participate)
    const int pch = t & 3;           // 16B chunk (4 chunks = 64 B)
    const __nv_bfloat16* pg0 = g_proto + (size_t)prr * K_DIM + k0 + pch * 8;

    // issue loads for one stage/chunk
    auto issue = [&](int stage, int chunk) {
        const float* xg = xg0 + chunk * KB;
        uint32_t a_base = As_u + (uint32_t)(stage * AS_STAGE) * 4;
        #pragma unroll
        for (int pass = 0; pass < 4; pass++) {
            cpa16(a_base + (uint32_t)((xrr + pass * 32) * APITCH + xch * 4) * 4,
                  xg + (size_t)(pass * 32) * K_DIM);
        }
        if (prr < NP) {
            cpa16(Bs_u + (uint32_t)(stage * BS_STAGE + prr * BPITCH + pch * 8) * 2,
                  pg0 + chunk * KB);
        }
        cpa_commit();
    };

    // prologue: stages 0,1
    issue(0, 0);
    issue(1, 1);

    // fragment row indices
    const int r0 = warp * 16 + (lane >> 2);
    const int r1 = r0 + 8;

    float acc[7][4];
    #pragma unroll
    for (int j = 0; j < 7; j++)
        #pragma unroll
        for (int c = 0; c < 4; c++) acc[j][c] = 0.f;
    float x2a = 0.f, x2b = 0.f;

    for (int it = 0; it < NITER; ++it) {
        __syncthreads();                       // stage (it+2)%3 free to overwrite
        const int nxt = it + 2;
        if (nxt < NITER) issue(nxt % STAGES, nxt);
        else             cpa_commit();         // keep group counting uniform
        cpa_wait2();                           // chunk `it` arrived
        __syncthreads();

        const int stage = it % STAGES;
        const float* a_s = As + stage * AS_STAGE;
        const __nv_bfloat16* b_s = Bs + stage * BS_STAGE;

        #pragma unroll
        for (int kk = 0; kk < 2; ++kk) {
            const int kb = kk * 16 + q * 2;
            float2 a00 = *(const float2*)&a_s[r0 * APITCH + kb];
            float2 a01 = *(const float2*)&a_s[r0 * APITCH + kb + 8];
            float2 a10 = *(const float2*)&a_s[r1 * APITCH + kb];
            float2 a11 = *(const float2*)&a_s[r1 * APITCH + kb + 8];
            x2a += a00.x * a00.x + a00.y * a00.y + a01.x * a01.x + a01.y * a01.y;
            x2b += a10.x * a10.x + a10.y * a10.y + a11.x * a11.x + a11.y * a11.y;
            uint32_t A0 = pack_bf16x2(a00);
            uint32_t A1 = pack_bf16x2(a10);
            uint32_t A2 = pack_bf16x2(a01);
            uint32_t A3 = pack_bf16x2(a11);
            #pragma unroll
            for (int j = 0; j < 7; j++) {
                const int n = j * 8 + (lane >> 2);
                uint32_t B0 = *(const uint32_t*)&b_s[n * BPITCH + kb];
                uint32_t B1 = *(const uint32_t*)&b_s[n * BPITCH + kb + 8];
                asm volatile(
                    "mma.sync.aligned.m16n8k16.row.col.f32.bf16.bf16.f32 "
                    "{%0,%1,%2,%3}, {%4,%5,%6,%7}, {%8,%9}, {%0,%1,%2,%3};\n"
                    : "+f"(acc[j][0]), "+f"(acc[j][1]), "+f"(acc[j][2]), "+f"(acc[j][3])
                    : "r"(A0), "r"(A1), "r"(A2), "r"(A3), "r"(B0), "r"(B1));
            }
        }
    }

    // write xp partials (private scratch slice per block — deterministic)
    float* outp = g_xp + ((size_t)ks * MTILES + mt) * (MT * NP);
    const int ccol = q * 2;
    #pragma unroll
    for (int j = 0; j < 7; j++) {
        const int n = j * 8 + ccol;
        *(float2*)&outp[(size_t)r0 * NP + n] = make_float2(acc[j][0], acc[j][1]);
        *(float2*)&outp[(size_t)r1 * NP + n] = make_float2(acc[j][2], acc[j][3]);
    }

    // x^2 partials: quad reduce (lanes differ only in k coverage)
    x2a += __shfl_xor_sync(0xffffffffu, x2a, 1);
    x2a += __shfl_xor_sync(0xffffffffu, x2a, 2);
    x2b += __shfl_xor_sync(0xffffffffu, x2b, 1);
    x2b += __shfl_xor_sync(0xffffffffu, x2b, 2);
    if (q == 0) {
        g_x2[(size_t)ks * B_DIM + b0 + r0] = x2a;
        g_x2[(size_t)ks * B_DIM + b0 + r1] = x2b;
    }
}

// ---------------------------------------------------------------------------
// Kernel 3: reduce split-K partials + p2 partials, relu(x2 + p2 - 2*xp)
// ---------------------------------------------------------------------------
__global__ void __launch_bounds__(64) epilogue_kernel(float* __restrict__ out) {
    const int b = blockIdx.x;
    const int p = threadIdx.x;   // 0..63
    const int mt = b >> 7, r = b & 127;

    float xp = 0.f;
    if (p < NP) {
        #pragma unroll
        for (int ks = 0; ks < KS; ++ks)
            xp += g_xp[((size_t)ks * MTILES + mt) * (MT * NP) + (size_t)r * NP + p];
    }

    __shared__ float x2sh;
    if (p < 32) {
        float s = (p < KS) ? g_x2[(size_t)p * B_DIM + b] : 0.f;
        #pragma unroll
        for (int off = 16; off > 0; off >>= 1)
            s += __shfl_xor_sync(0xffffffffu, s, off);
        if (p == 0) x2sh = s;
    }
    __syncthreads();

    if (p < P_DIM) {
        float p2 = 0.f;
        #pragma unroll
        for (int c = 0; c < 8; c++) p2 += g_p2p[c][p];
        float d = x2sh + p2 - 2.f * xp;
        out[(size_t)b * P_DIM + p] = d > 0.f ? d : 0.f;
    }
}

// ---------------------------------------------------------------------------
extern "C" void kernel_launch(void* const* d_in, const int* in_sizes, int n_in,
                              void* d_out, int out_size) {
    const float* x     = (const float*)d_in[0];
    const float* proto = (const float*)d_in[1];
    if (in_sizes[0] == P_DIM * K_DIM) {  // defensive: swap if order differs
        x     = (const float*)d_in[1];
        proto = (const float*)d_in[0];
    }
    float* out = (float*)d_out;

    cudaFuncSetAttribute(gemm_kernel,
                         cudaFuncAttributeMaxDynamicSharedMemorySize, SMEM_BYTES);

    prep_kernel<<<dim3(NP, 8), 128>>>(proto);
    gemm_kernel<<<dim3(MTILES, KS), 256, SMEM_BYTES>>>(x);
    epilogue_kernel<<<B_DIM, 64>>>(out);
}